// round 6
// baseline (speedup 1.0000x reference)
#include <cuda_runtime.h>
#include <cuda_bf16.h>

#define NN   8192
#define FIN  256
#define H1   128
#define H2   64
#define F2   128
#define K3   192          // hi|hi|lo split K for zzt
#define EMAX 393216

// ---------------- persistent scratch ----------------
static __device__ float g_dinv[NN];
static __device__ int   g_count[NN];
static __device__ int   g_beg[NN];
static __device__ int   g_end[NN];
static __device__ int   g_cursor[NN];
static __device__ int   g_total;
static __device__ int   g_is64;
static __device__ int   g_csr[EMAX];
static __device__ float g_bias2[F2];                 // bm || bs
static __device__ __nv_bfloat16 g_ha[NN * 256];      // h split: [hi(128) | lo(128)]
static __device__ __nv_bfloat16 g_za[NN * K3];       // [hi | hi | lo]
static __device__ __nv_bfloat16 g_zb[NN * K3];       // [hi | lo | hi]

// fp32 intermediates inside d_out (64M floats); consumed before zzt overwrites
#define OFF_HLIN 0
#define OFF_L2   (1 << 20)

// ---------------- 1: sniff dtype + zero counters ----------------
static __global__ void vg_sniff_zero(const unsigned* __restrict__ ei_w) {
    int i = blockIdx.x * blockDim.x + threadIdx.x;
    if (i < NN) g_count[i] = 0;
    if (i == 0) g_total = 0;
    if (blockIdx.x == 0) {
        __shared__ int any_nonzero;
        if (threadIdx.x == 0) any_nonzero = 0;
        __syncthreads();
        unsigned w = ei_w[2 * threadIdx.x + 1];     // high word if int64
        if (w != 0) atomicOr(&any_nonzero, 1);
        __syncthreads();
        if (threadIdx.x == 0) g_is64 = any_nonzero ? 0 : 1;
    }
}

static __device__ __forceinline__ int edge_at(const void* ei, int idx) {
    int v;
    if (g_is64) v = (int)((const long long*)ei)[idx];
    else        v = ((const int*)ei)[idx];
    return (v < 0) ? 0 : (v >= NN ? NN - 1 : v);
}

// ---------------- 2: count ----------------
static __global__ void vg_count_edges(const void* __restrict__ ei, int E) {
    int e = blockIdx.x * blockDim.x + threadIdx.x;
    if (e < E) atomicAdd(&g_count[edge_at(ei, E + e)], 1);   // dst
}

// ---------------- 3: ranges + dinv + bias pack ----------------
static __global__ void vg_alloc_ranges(const float* __restrict__ bm,
                                       const float* __restrict__ bs) {
    int i = blockIdx.x * blockDim.x + threadIdx.x;
    if (i < F2) g_bias2[i] = (i < H2) ? bm[i] : bs[i - H2];
    if (i >= NN) return;
    int c = g_count[i];
    g_dinv[i] = rsqrtf((float)(c + 1));
    int o = atomicAdd(&g_total, c);
    g_beg[i] = o;
    g_cursor[i] = o;
    g_end[i] = o + c;
}

// ---------------- 4: scatter ----------------
static __global__ void vg_scatter_edges(const void* __restrict__ ei, int E) {
    int e = blockIdx.x * blockDim.x + threadIdx.x;
    if (e < E) {
        int d = edge_at(ei, E + e);
        int s = edge_at(ei, e);
        int pos = atomicAdd(&g_cursor[d], 1);
        if (pos < EMAX) g_csr[pos] = s;
    }
}

// ---------------- aggregation core: one warp per dst node, 128 feats ----------------
static __device__ __forceinline__ void agg_core(const float* __restrict__ lin,
                                                int d, int lane,
                                                float& ax, float& ay, float& az, float& aw) {
    int p = g_beg[d], end = g_end[d];
    float did = g_dinv[d];
    ax = ay = az = aw = 0.f;
    int c4 = lane * 4;
    for (; p + 3 < end; p += 4) {
        int s0 = g_csr[p], s1 = g_csr[p + 1], s2 = g_csr[p + 2], s3 = g_csr[p + 3];
        float w0 = did * g_dinv[s0];
        float w1 = did * g_dinv[s1];
        float w2 = did * g_dinv[s2];
        float w3 = did * g_dinv[s3];
        float4 v0 = *(const float4*)&lin[s0 * H1 + c4];
        float4 v1 = *(const float4*)&lin[s1 * H1 + c4];
        float4 v2 = *(const float4*)&lin[s2 * H1 + c4];
        float4 v3 = *(const float4*)&lin[s3 * H1 + c4];
        ax += w0 * v0.x; ay += w0 * v0.y; az += w0 * v0.z; aw += w0 * v0.w;
        ax += w1 * v1.x; ay += w1 * v1.y; az += w1 * v1.z; aw += w1 * v1.w;
        ax += w2 * v2.x; ay += w2 * v2.y; az += w2 * v2.z; aw += w2 * v2.w;
        ax += w3 * v3.x; ay += w3 * v3.y; az += w3 * v3.z; aw += w3 * v3.w;
    }
    for (; p < end; p++) {
        int s = g_csr[p];
        float w = did * g_dinv[s];
        float4 v = *(const float4*)&lin[s * H1 + c4];
        ax += w * v.x; ay += w * v.y; az += w * v.z; aw += w * v.w;
    }
    float w = did * did;   // self loop
    float4 v = *(const float4*)&lin[d * H1 + c4];
    ax += w * v.x; ay += w * v.y; az += w * v.z; aw += w * v.w;
}

// 6: agg1 — aggregates hlin, emits h as bf16 hi/lo packs
static __global__ void __launch_bounds__(256)
vg_agg1(const float* __restrict__ b0, const float* __restrict__ scratch) {
    int warp = (blockIdx.x * blockDim.x + threadIdx.x) >> 5;
    int lane = threadIdx.x & 31;
    if (warp >= NN) return;
    float ax, ay, az, aw;
    agg_core(scratch + OFF_HLIN, warp, lane, ax, ay, az, aw);
    int c4 = lane * 4;
    float4 b = *(const float4*)&b0[c4];
    ax += b.x; ay += b.y; az += b.z; aw += b.w;
    __nv_bfloat16 hx = __float2bfloat16(ax), hy = __float2bfloat16(ay);
    __nv_bfloat16 hz = __float2bfloat16(az), hw = __float2bfloat16(aw);
    __nv_bfloat16 lx = __float2bfloat16(ax - __bfloat162float(hx));
    __nv_bfloat16 ly = __float2bfloat16(ay - __bfloat162float(hy));
    __nv_bfloat16 lz = __float2bfloat16(az - __bfloat162float(hz));
    __nv_bfloat16 lw = __float2bfloat16(aw - __bfloat162float(hw));
    int base = warp * 256 + c4;
    *(__nv_bfloat162*)&g_ha[base]           = __nv_bfloat162{hx, hy};
    *(__nv_bfloat162*)&g_ha[base + 2]       = __nv_bfloat162{hz, hw};
    *(__nv_bfloat162*)&g_ha[base + 128]     = __nv_bfloat162{lx, ly};
    *(__nv_bfloat162*)&g_ha[base + 130]     = __nv_bfloat162{lz, lw};
}

// 8: agg2 — aggregates l2, fused reparameterize + z split packs
static __global__ void __launch_bounds__(256)
vg_agg2_z(const float* __restrict__ noise, const float* __restrict__ scratch) {
    int warp = (blockIdx.x * blockDim.x + threadIdx.x) >> 5;
    int lane = threadIdx.x & 31;
    if (warp >= NN) return;
    float ax, ay, az, aw;
    agg_core(scratch + OFF_L2, warp, lane, ax, ay, az, aw);
    int c4 = lane * 4;
    ax += g_bias2[c4];
    ay += g_bias2[c4 + 1];
    az += g_bias2[c4 + 2];
    aw += g_bias2[c4 + 3];
    // lanes 0..15 hold mean[4l..4l+3]; lanes 16..31 hold log_std of same features
    float sx = __shfl_down_sync(0xffffffffu, ax, 16);
    float sy = __shfl_down_sync(0xffffffffu, ay, 16);
    float sz = __shfl_down_sync(0xffffffffu, az, 16);
    float sw = __shfl_down_sync(0xffffffffu, aw, 16);
    if (lane < 16) {
        int f = c4;                       // 0..60
        float4 nz = *(const float4*)&noise[warp * H2 + f];
        float z0 = ax + nz.x * __expf(sx);
        float z1 = ay + nz.y * __expf(sy);
        float z2 = az + nz.z * __expf(sz);
        float z3 = aw + nz.w * __expf(sw);
        __nv_bfloat16 h0 = __float2bfloat16(z0), h1 = __float2bfloat16(z1);
        __nv_bfloat16 h2 = __float2bfloat16(z2), h3 = __float2bfloat16(z3);
        __nv_bfloat16 l0 = __float2bfloat16(z0 - __bfloat162float(h0));
        __nv_bfloat16 l1 = __float2bfloat16(z1 - __bfloat162float(h1));
        __nv_bfloat16 l2 = __float2bfloat16(z2 - __bfloat162float(h2));
        __nv_bfloat16 l3 = __float2bfloat16(z3 - __bfloat162float(h3));
        int base = warp * K3 + f;
        __nv_bfloat162 hp0{h0, h1}, hp1{h2, h3}, lp0{l0, l1}, lp1{l2, l3};
        // A = [hi | hi | lo]
        *(__nv_bfloat162*)&g_za[base]       = hp0;
        *(__nv_bfloat162*)&g_za[base + 2]   = hp1;
        *(__nv_bfloat162*)&g_za[base + 64]  = hp0;
        *(__nv_bfloat162*)&g_za[base + 66]  = hp1;
        *(__nv_bfloat162*)&g_za[base + 128] = lp0;
        *(__nv_bfloat162*)&g_za[base + 130] = lp1;
        // B = [hi | lo | hi]
        *(__nv_bfloat162*)&g_zb[base]       = hp0;
        *(__nv_bfloat162*)&g_zb[base + 2]   = hp1;
        *(__nv_bfloat162*)&g_zb[base + 64]  = lp0;
        *(__nv_bfloat162*)&g_zb[base + 66]  = lp1;
        *(__nv_bfloat162*)&g_zb[base + 128] = hp0;
        *(__nv_bfloat162*)&g_zb[base + 130] = hp1;
    }
}

// ---------------- tensor-core GEMM epilogue-shared mma tile (64x128, 256 thr) ----------------
// warp layout: 8 warps, wm=wid>>1 (16-row tiles), wn=wid&1 (64-col halves)
// As[64][PADK], Bs[128][PADK], inner K = 96 per fp32-32 chunk (3-term split)
#define PADK 112

static __device__ __forceinline__ void mma_chunk(
    const __nv_bfloat16 (*As)[PADK], const __nv_bfloat16 (*Bs)[PADK],
    int wm, int wn, int g, int tg, float acc[8][4]) {
    #pragma unroll
    for (int kk = 0; kk < 96; kk += 16) {
        int row = 16 * wm;
        unsigned a0 = *(const unsigned*)&As[row + g    ][kk + 2 * tg];
        unsigned a1 = *(const unsigned*)&As[row + g + 8][kk + 2 * tg];
        unsigned a2 = *(const unsigned*)&As[row + g    ][kk + 2 * tg + 8];
        unsigned a3 = *(const unsigned*)&As[row + g + 8][kk + 2 * tg + 8];
        #pragma unroll
        for (int nj = 0; nj < 8; nj++) {
            int col = 64 * wn + 8 * nj + g;
            unsigned b0 = *(const unsigned*)&Bs[col][kk + 2 * tg];
            unsigned b1 = *(const unsigned*)&Bs[col][kk + 2 * tg + 8];
            asm volatile(
                "mma.sync.aligned.m16n8k16.row.col.f32.bf16.bf16.f32 "
                "{%0,%1,%2,%3}, {%4,%5,%6,%7}, {%8,%9}, {%0,%1,%2,%3};"
                : "+f"(acc[nj][0]), "+f"(acc[nj][1]),
                  "+f"(acc[nj][2]), "+f"(acc[nj][3])
                : "r"(a0), "r"(a1), "r"(a2), "r"(a3), "r"(b0), "r"(b1));
        }
    }
}

// 5: hlin = features @ W0 (K=256 fp32, split inline)
static __global__ void __launch_bounds__(256)
vg_gemm1_tc(const float* __restrict__ features, const float* __restrict__ W0,
            float* __restrict__ scratch) {
    __shared__ __nv_bfloat16 As[64][PADK];
    __shared__ __nv_bfloat16 Bs[128][PADK];
    int tid = threadIdx.x;
    int wid = tid >> 5, lane = tid & 31;
    int wm = wid >> 1, wn = wid & 1;
    int g = lane >> 2, tg = lane & 3;
    int row0 = blockIdx.x * 64;
    float acc[8][4] = {};
    for (int c = 0; c < FIN / 32; c++) {
        // A: 64 rows x 32 fp32 -> hi/lo/hi
        #pragma unroll
        for (int r = 0; r < 2; r++) {
            int i = tid + r * 256;
            int m = i >> 3, kk = (i & 7) * 4;
            float4 v = *(const float4*)&features[(row0 + m) * FIN + c * 32 + kk];
            float vv[4] = {v.x, v.y, v.z, v.w};
            #pragma unroll
            for (int e = 0; e < 4; e++) {
                __nv_bfloat16 hi = __float2bfloat16(vv[e]);
                __nv_bfloat16 lo = __float2bfloat16(vv[e] - __bfloat162float(hi));
                As[m][kk + e]      = hi;
                As[m][32 + kk + e] = lo;
                As[m][64 + kk + e] = hi;
            }
        }
        // B: 32 k-rows x 128 cols -> whi/whi/wlo (transposed into Bs[n][k])
        #pragma unroll
        for (int r = 0; r < 4; r++) {
            int i = tid + r * 256;
            int kk = i >> 5, n = (i & 31) * 4;
            float4 w = *(const float4*)&W0[(c * 32 + kk) * H1 + n];
            float ww[4] = {w.x, w.y, w.z, w.w};
            #pragma unroll
            for (int e = 0; e < 4; e++) {
                __nv_bfloat16 hi = __float2bfloat16(ww[e]);
                __nv_bfloat16 lo = __float2bfloat16(ww[e] - __bfloat162float(hi));
                Bs[n + e][kk]      = hi;
                Bs[n + e][32 + kk] = hi;
                Bs[n + e][64 + kk] = lo;
            }
        }
        __syncthreads();
        mma_chunk(As, Bs, wm, wn, g, tg, acc);
        __syncthreads();
    }
    float* C = scratch + OFF_HLIN;
    int row = row0 + 16 * wm + g;
    #pragma unroll
    for (int nj = 0; nj < 8; nj++) {
        int col = 64 * wn + 8 * nj + 2 * tg;
        *(float2*)&C[row * H1 + col]       = make_float2(acc[nj][0], acc[nj][1]);
        *(float2*)&C[(row + 8) * H1 + col] = make_float2(acc[nj][2], acc[nj][3]);
    }
}

// 7: l2 = h @ [Wm | Ws]  (A already bf16 hi/lo packs; K=128 fp32-equivalent)
static __global__ void __launch_bounds__(256)
vg_gemm2_tc(const float* __restrict__ Wm, const float* __restrict__ Ws,
            float* __restrict__ scratch) {
    __shared__ __nv_bfloat16 As[64][PADK];
    __shared__ __nv_bfloat16 Bs[128][PADK];
    int tid = threadIdx.x;
    int wid = tid >> 5, lane = tid & 31;
    int wm = wid >> 1, wn = wid & 1;
    int g = lane >> 2, tg = lane & 3;
    int row0 = blockIdx.x * 64;
    float acc[8][4] = {};
    for (int c = 0; c < H1 / 32; c++) {
        // A: hi from g_ha[..][c*32..], lo from +128; layout [hi|lo|hi]
        for (int i = tid; i < 256; i += 256) {
            int m = i >> 2, kk = (i & 3) * 8;
            float4 hi4 = *(const float4*)&g_ha[(row0 + m) * 256 + c * 32 + kk];
            float4 lo4 = *(const float4*)&g_ha[(row0 + m) * 256 + 128 + c * 32 + kk];
            *(float4*)&As[m][kk]      = hi4;
            *(float4*)&As[m][32 + kk] = lo4;
            *(float4*)&As[m][64 + kk] = hi4;
        }
        // B: combined [Wm | Ws] rows k -> whi/whi/wlo
        #pragma unroll
        for (int r = 0; r < 4; r++) {
            int i = tid + r * 256;
            int kk = i >> 5, n = (i & 31) * 4;
            int k = c * 32 + kk;
            float4 w = (n < 64) ? *(const float4*)&Wm[k * H2 + n]
                                : *(const float4*)&Ws[k * H2 + (n - 64)];
            float ww[4] = {w.x, w.y, w.z, w.w};
            #pragma unroll
            for (int e = 0; e < 4; e++) {
                __nv_bfloat16 hi = __float2bfloat16(ww[e]);
                __nv_bfloat16 lo = __float2bfloat16(ww[e] - __bfloat162float(hi));
                Bs[n + e][kk]      = hi;
                Bs[n + e][32 + kk] = hi;
                Bs[n + e][64 + kk] = lo;
            }
        }
        __syncthreads();
        mma_chunk(As, Bs, wm, wn, g, tg, acc);
        __syncthreads();
    }
    float* C = scratch + OFF_L2;
    int row = row0 + 16 * wm + g;
    #pragma unroll
    for (int nj = 0; nj < 8; nj++) {
        int col = 64 * wn + 8 * nj + 2 * tg;
        *(float2*)&C[row * F2 + col]       = make_float2(acc[nj][0], acc[nj][1]);
        *(float2*)&C[(row + 8) * F2 + col] = make_float2(acc[nj][2], acc[nj][3]);
    }
}

// ---------------- 9: C = sigmoid(Z Z^T) via bf16 mma, K=192, symmetric ----------------
#define ZBK 32
#define ZPAD 8
static __global__ void __launch_bounds__(256)
vg_zzt_mma(float* __restrict__ C) {
    int bi = blockIdx.y, bj = blockIdx.x;
    if (bj < bi) return;
    __shared__ __nv_bfloat16 As[128][ZBK + ZPAD];
    __shared__ __nv_bfloat16 Bs[128][ZBK + ZPAD];
    int tid = threadIdx.x;
    int wid = tid >> 5;
    int lane = tid & 31;
    int wm = wid >> 1;
    int wn = wid & 1;
    int g  = lane >> 2;
    int tg = lane & 3;
    int ri = bi * 128, rj = bj * 128;

    float acc[2][8][4];
    #pragma unroll
    for (int a = 0; a < 2; a++)
        #pragma unroll
        for (int b = 0; b < 8; b++)
            #pragma unroll
            for (int c = 0; c < 4; c++) acc[a][b][c] = 0.f;

    for (int k0 = 0; k0 < K3; k0 += ZBK) {
        #pragma unroll
        for (int r = 0; r < 2; r++) {
            int i = tid + r * 256;
            int m = i >> 2;
            int kk = (i & 3) * 8;
            *(float4*)&As[m][kk] = *(const float4*)&g_za[(ri + m) * K3 + k0 + kk];
            *(float4*)&Bs[m][kk] = *(const float4*)&g_zb[(rj + m) * K3 + k0 + kk];
        }
        __syncthreads();
        #pragma unroll
        for (int kk = 0; kk < ZBK; kk += 16) {
            unsigned a0[2], a1[2], a2[2], a3[2];
            #pragma unroll
            for (int mi = 0; mi < 2; mi++) {
                int row = 32 * wm + 16 * mi;
                a0[mi] = *(const unsigned*)&As[row + g    ][kk + 2 * tg];
                a1[mi] = *(const unsigned*)&As[row + g + 8][kk + 2 * tg];
                a2[mi] = *(const unsigned*)&As[row + g    ][kk + 2 * tg + 8];
                a3[mi] = *(const unsigned*)&As[row + g + 8][kk + 2 * tg + 8];
            }
            #pragma unroll
            for (int nj = 0; nj < 8; nj++) {
                int col = 64 * wn + 8 * nj + g;
                unsigned b0 = *(const unsigned*)&Bs[col][kk + 2 * tg];
                unsigned b1 = *(const unsigned*)&Bs[col][kk + 2 * tg + 8];
                #pragma unroll
                for (int mi = 0; mi < 2; mi++) {
                    asm volatile(
                        "mma.sync.aligned.m16n8k16.row.col.f32.bf16.bf16.f32 "
                        "{%0,%1,%2,%3}, {%4,%5,%6,%7}, {%8,%9}, {%0,%1,%2,%3};"
                        : "+f"(acc[mi][nj][0]), "+f"(acc[mi][nj][1]),
                          "+f"(acc[mi][nj][2]), "+f"(acc[mi][nj][3])
                        : "r"(a0[mi]), "r"(a1[mi]), "r"(a2[mi]), "r"(a3[mi]),
                          "r"(b0), "r"(b1));
                }
            }
        }
        __syncthreads();
    }

    #pragma unroll
    for (int mi = 0; mi < 2; mi++)
        #pragma unroll
        for (int nj = 0; nj < 8; nj++)
            #pragma unroll
            for (int c = 0; c < 4; c++) {
                float v = acc[mi][nj][c];
                float r = 1.0f / (1.0f + __expf(-v));
                acc[mi][nj][c] = (r == r) ? r : 0.0f;
            }

    #pragma unroll
    for (int mi = 0; mi < 2; mi++) {
        int row = ri + 32 * wm + 16 * mi + g;
        #pragma unroll
        for (int nj = 0; nj < 8; nj++) {
            int col = rj + 64 * wn + 8 * nj + 2 * tg;
            *(float2*)&C[(long long)row * NN + col] =
                make_float2(acc[mi][nj][0], acc[mi][nj][1]);
            *(float2*)&C[(long long)(row + 8) * NN + col] =
                make_float2(acc[mi][nj][2], acc[mi][nj][3]);
        }
    }
    if (bi != bj) {
        #pragma unroll
        for (int mi = 0; mi < 2; mi++) {
            int colm = ri + 32 * wm + 16 * mi + g;
            #pragma unroll
            for (int nj = 0; nj < 8; nj++) {
                int rowm = rj + 64 * wn + 8 * nj + 2 * tg;
                C[(long long)rowm * NN + colm]           = acc[mi][nj][0];
                C[(long long)(rowm + 1) * NN + colm]     = acc[mi][nj][1];
                C[(long long)rowm * NN + colm + 8]       = acc[mi][nj][2];
                C[(long long)(rowm + 1) * NN + colm + 8] = acc[mi][nj][3];
            }
        }
    }
}

// ---------------- launch ----------------
extern "C" void kernel_launch(void* const* d_in, const int* in_sizes, int n_in,
                              void* d_out, int out_size) {
    const float* features = (const float*)d_in[0];
    const void*  ei       = d_in[1];
    const float* noise    = (const float*)d_in[2];
    const float* W0       = (const float*)d_in[3];
    const float* b0       = (const float*)d_in[4];
    const float* Wm       = (const float*)d_in[5];
    const float* bm       = (const float*)d_in[6];
    const float* Ws       = (const float*)d_in[7];
    const float* bs       = (const float*)d_in[8];
    int E = in_sizes[1] / 2;
    float* out = (float*)d_out;

    int eb = (E + 255) / 256;

    vg_sniff_zero<<<NN / 256, 256>>>((const unsigned*)ei);       // 1
    vg_count_edges<<<eb, 256>>>(ei, E);                          // 2
    vg_alloc_ranges<<<NN / 256, 256>>>(bm, bs);                  // 3
    vg_scatter_edges<<<eb, 256>>>(ei, E);                        // 4

    vg_gemm1_tc<<<NN / 64, 256>>>(features, W0, out);            // 5
    vg_agg1<<<NN / 8, 256>>>(b0, out);                           // 6 (profiled by ncu)

    vg_gemm2_tc<<<NN / 64, 256>>>(Wm, Ws, out);                  // 7
    vg_agg2_z<<<NN / 8, 256>>>(noise, out);                      // 8

    vg_zzt_mma<<<dim3(64, 64), 256>>>(out);                      // 9
}

// round 8
// speedup vs baseline: 1.2314x; 1.2314x over previous
#include <cuda_runtime.h>
#include <cuda_bf16.h>

#define NN   8192
#define FIN  256
#define H1   128
#define H2   64
#define F2   128
#define K3   192          // hi|hi|lo split K for zzt
#define CAP  192          // per-node CSR bucket capacity (Poisson(48): P(>192)~0)

// ---------------- persistent scratch ----------------
static __device__ float g_dinv[NN];
static __device__ int   g_count[NN];
static __device__ int   g_is64;
static __device__ int   g_csr[NN * CAP];             // bucketed by dst
static __device__ float g_bias2[F2];                 // bm || bs
static __device__ __nv_bfloat16 g_za[NN * K3];       // [hi | hi | lo]
static __device__ __nv_bfloat16 g_zb[NN * K3];       // [hi | lo | hi]

// fp32 intermediates inside d_out (64M floats); consumed before zzt overwrites
#define OFF_HLIN 0
#define OFF_H    (1 << 20)
#define OFF_L2   (2 << 20)

// ---------------- 1: sniff dtype + zero counters ----------------
static __global__ void vg_sniff_zero(const unsigned* __restrict__ ei_w) {
    int i = blockIdx.x * blockDim.x + threadIdx.x;
    if (i < NN) g_count[i] = 0;
    if (blockIdx.x == 0) {
        __shared__ int any_nonzero;
        if (threadIdx.x == 0) any_nonzero = 0;
        __syncthreads();
        unsigned w = ei_w[2 * threadIdx.x + 1];     // high word if int64
        if (w != 0) atomicOr(&any_nonzero, 1);
        __syncthreads();
        if (threadIdx.x == 0) g_is64 = any_nonzero ? 0 : 1;
    }
}

static __device__ __forceinline__ int edge_at(const void* ei, int idx) {
    int v;
    if (g_is64) v = (int)((const long long*)ei)[idx];
    else        v = ((const int*)ei)[idx];
    return (v < 0) ? 0 : (v >= NN ? NN - 1 : v);
}

// ---------------- 2: single-pass bucketed CSR build ----------------
static __global__ void vg_build(const void* __restrict__ ei, int E) {
    int e = blockIdx.x * blockDim.x + threadIdx.x;
    if (e < E) {
        int d = edge_at(ei, E + e);      // dst
        int s = edge_at(ei, e);          // src
        int c = atomicAdd(&g_count[d], 1);
        if (c < CAP) g_csr[d * CAP + c] = s;
    }
}

// ---------------- 3: dinv + bias pack ----------------
static __global__ void vg_dinv(const float* __restrict__ bm,
                               const float* __restrict__ bs) {
    int i = blockIdx.x * blockDim.x + threadIdx.x;
    if (i < F2) g_bias2[i] = (i < H2) ? bm[i] : bs[i - H2];
    if (i < NN) g_dinv[i] = rsqrtf((float)(g_count[i] + 1));   // +1 self loop
}

// ---------------- aggregation core: one warp per dst node, 128 feats ----------------
static __device__ __forceinline__ void agg_core(const float* __restrict__ lin,
                                                int d, int lane,
                                                float& ax, float& ay, float& az, float& aw) {
    int cnt = g_count[d];
    if (cnt > CAP) cnt = CAP;
    const int* bucket = &g_csr[d * CAP];
    float did = g_dinv[d];
    ax = ay = az = aw = 0.f;
    int c4 = lane * 4;
    int p = 0;
    for (; p + 3 < cnt; p += 4) {
        int s0 = bucket[p], s1 = bucket[p + 1], s2 = bucket[p + 2], s3 = bucket[p + 3];
        float w0 = did * g_dinv[s0];
        float w1 = did * g_dinv[s1];
        float w2 = did * g_dinv[s2];
        float w3 = did * g_dinv[s3];
        float4 v0 = *(const float4*)&lin[s0 * H1 + c4];
        float4 v1 = *(const float4*)&lin[s1 * H1 + c4];
        float4 v2 = *(const float4*)&lin[s2 * H1 + c4];
        float4 v3 = *(const float4*)&lin[s3 * H1 + c4];
        ax += w0 * v0.x; ay += w0 * v0.y; az += w0 * v0.z; aw += w0 * v0.w;
        ax += w1 * v1.x; ay += w1 * v1.y; az += w1 * v1.z; aw += w1 * v1.w;
        ax += w2 * v2.x; ay += w2 * v2.y; az += w2 * v2.z; aw += w2 * v2.w;
        ax += w3 * v3.x; ay += w3 * v3.y; az += w3 * v3.z; aw += w3 * v3.w;
    }
    for (; p < cnt; p++) {
        int s = bucket[p];
        float w = did * g_dinv[s];
        float4 v = *(const float4*)&lin[s * H1 + c4];
        ax += w * v.x; ay += w * v.y; az += w * v.z; aw += w * v.w;
    }
    float w = did * did;   // self loop
    float4 v = *(const float4*)&lin[d * H1 + c4];
    ax += w * v.x; ay += w * v.y; az += w * v.z; aw += w * v.w;
}

// 5: agg1 — aggregates hlin -> fp32 h (+b0)
static __global__ void __launch_bounds__(256)
vg_agg1(const float* __restrict__ b0, float* __restrict__ scratch) {
    int warp = (blockIdx.x * blockDim.x + threadIdx.x) >> 5;
    int lane = threadIdx.x & 31;
    if (warp >= NN) return;
    float ax, ay, az, aw;
    agg_core(scratch + OFF_HLIN, warp, lane, ax, ay, az, aw);
    int c4 = lane * 4;
    float4 b = *(const float4*)&b0[c4];
    float4 r = make_float4(ax + b.x, ay + b.y, az + b.z, aw + b.w);
    *(float4*)&(scratch + OFF_H)[warp * H1 + c4] = r;
}

// 7: agg2 — aggregates l2, fused reparameterize + z split packs
static __global__ void __launch_bounds__(256)
vg_agg2_z(const float* __restrict__ noise, const float* __restrict__ scratch) {
    int warp = (blockIdx.x * blockDim.x + threadIdx.x) >> 5;
    int lane = threadIdx.x & 31;
    if (warp >= NN) return;
    float ax, ay, az, aw;
    agg_core(scratch + OFF_L2, warp, lane, ax, ay, az, aw);
    int c4 = lane * 4;
    ax += g_bias2[c4];
    ay += g_bias2[c4 + 1];
    az += g_bias2[c4 + 2];
    aw += g_bias2[c4 + 3];
    // lanes 0..15 hold mean[4l..4l+3]; lanes 16..31 hold log_std of same features
    float sx = __shfl_down_sync(0xffffffffu, ax, 16);
    float sy = __shfl_down_sync(0xffffffffu, ay, 16);
    float sz = __shfl_down_sync(0xffffffffu, az, 16);
    float sw = __shfl_down_sync(0xffffffffu, aw, 16);
    if (lane < 16) {
        int f = c4;                       // 0..60
        float4 nz = *(const float4*)&noise[warp * H2 + f];
        float z0 = ax + nz.x * __expf(sx);
        float z1 = ay + nz.y * __expf(sy);
        float z2 = az + nz.z * __expf(sz);
        float z3 = aw + nz.w * __expf(sw);
        __nv_bfloat16 h0 = __float2bfloat16(z0), h1 = __float2bfloat16(z1);
        __nv_bfloat16 h2 = __float2bfloat16(z2), h3 = __float2bfloat16(z3);
        __nv_bfloat16 l0 = __float2bfloat16(z0 - __bfloat162float(h0));
        __nv_bfloat16 l1 = __float2bfloat16(z1 - __bfloat162float(h1));
        __nv_bfloat16 l2 = __float2bfloat16(z2 - __bfloat162float(h2));
        __nv_bfloat16 l3 = __float2bfloat16(z3 - __bfloat162float(h3));
        int base = warp * K3 + f;
        __nv_bfloat162 hp0{h0, h1}, hp1{h2, h3}, lp0{l0, l1}, lp1{l2, l3};
        // A = [hi | hi | lo]
        *(__nv_bfloat162*)&g_za[base]       = hp0;
        *(__nv_bfloat162*)&g_za[base + 2]   = hp1;
        *(__nv_bfloat162*)&g_za[base + 64]  = hp0;
        *(__nv_bfloat162*)&g_za[base + 66]  = hp1;
        *(__nv_bfloat162*)&g_za[base + 128] = lp0;
        *(__nv_bfloat162*)&g_za[base + 130] = lp1;
        // B = [hi | lo | hi]
        *(__nv_bfloat162*)&g_zb[base]       = hp0;
        *(__nv_bfloat162*)&g_zb[base + 2]   = hp1;
        *(__nv_bfloat162*)&g_zb[base + 64]  = lp0;
        *(__nv_bfloat162*)&g_zb[base + 66]  = lp1;
        *(__nv_bfloat162*)&g_zb[base + 128] = hp0;
        *(__nv_bfloat162*)&g_zb[base + 130] = hp1;
    }
}

// ---------------- fp32 SGEMM body: C[M,N] = A[M,K] @ B[K,N] ----------------
template <int BM, int BN, int BK, int TM, int TN>
static __device__ __forceinline__ void sgemm_body(const float* __restrict__ A,
                                                  const float* __restrict__ B,
                                                  float* __restrict__ C,
                                                  int K, int ldb, int ldc, int col0) {
    constexpr int THREADS = (BM / TM) * (BN / TN);
    __shared__ float As[BK][BM + 4];
    __shared__ float Bs[BK][BN];
    int row0 = blockIdx.x * BM;
    int tid = threadIdx.x;
    int tcol = tid % (BN / TN);
    int trow = tid / (BN / TN);
    float acc[TM][TN] = {};
    for (int k0 = 0; k0 < K; k0 += BK) {
        for (int i = tid; i < BM * BK / 4; i += THREADS) {
            int m = i / (BK / 4);
            int kk = (i % (BK / 4)) * 4;
            float4 v = *(const float4*)&A[(row0 + m) * K + k0 + kk];
            As[kk + 0][m] = v.x; As[kk + 1][m] = v.y;
            As[kk + 2][m] = v.z; As[kk + 3][m] = v.w;
        }
        for (int i = tid; i < BK * BN / 4; i += THREADS) {
            int kk = i / (BN / 4);
            int n = (i % (BN / 4)) * 4;
            *(float4*)&Bs[kk][n] = *(const float4*)&B[(k0 + kk) * ldb + n];
        }
        __syncthreads();
        #pragma unroll
        for (int kk = 0; kk < BK; kk++) {
            float a[TM], b[TN];
            #pragma unroll
            for (int i = 0; i < TM; i++) a[i] = As[kk][trow * TM + i];
            #pragma unroll
            for (int j = 0; j < TN; j++) b[j] = Bs[kk][tcol * TN + j];
            #pragma unroll
            for (int i = 0; i < TM; i++)
                #pragma unroll
                for (int j = 0; j < TN; j++)
                    acc[i][j] += a[i] * b[j];
        }
        __syncthreads();
    }
    #pragma unroll
    for (int i = 0; i < TM; i++) {
        #pragma unroll
        for (int j = 0; j < TN; j += 4) {
            float4 v = make_float4(acc[i][j], acc[i][j + 1], acc[i][j + 2], acc[i][j + 3]);
            *(float4*)&C[(row0 + trow * TM + i) * ldc + col0 + tcol * TN + j] = v;
        }
    }
}

// 4: hlin = features @ W0 (K=256)
static __global__ void __launch_bounds__(256)
vg_gemm1(const float* __restrict__ features, const float* __restrict__ W0,
         float* __restrict__ scratch) {
    sgemm_body<64, 128, 32, 4, 8>(features, W0, scratch + OFF_HLIN, FIN, H1, H1, 0);
}

// 6: l2 = h @ [Wm | Ws] (two heads via blockIdx.y)
static __global__ void __launch_bounds__(256)
vg_gemm2(const float* __restrict__ Wm, const float* __restrict__ Ws,
         float* __restrict__ scratch) {
    const float* B = (blockIdx.y == 0) ? Wm : Ws;
    sgemm_body<64, 64, 32, 4, 4>(scratch + OFF_H, B, scratch + OFF_L2, H1, H2, F2,
                                 blockIdx.y * H2);
}

// ---------------- 8: C = sigmoid(Z Z^T) via bf16 mma, K=192, symmetric ----------------
#define ZBK 32
#define ZPAD 8
static __global__ void __launch_bounds__(256)
vg_zzt_mma(float* __restrict__ C) {
    int bi = blockIdx.y, bj = blockIdx.x;
    if (bj < bi) return;
    __shared__ __nv_bfloat16 As[128][ZBK + ZPAD];
    __shared__ __nv_bfloat16 Bs[128][ZBK + ZPAD];
    int tid = threadIdx.x;
    int wid = tid >> 5;
    int lane = tid & 31;
    int wm = wid >> 1;
    int wn = wid & 1;
    int g  = lane >> 2;
    int tg = lane & 3;
    int ri = bi * 128, rj = bj * 128;

    float acc[2][8][4];
    #pragma unroll
    for (int a = 0; a < 2; a++)
        #pragma unroll
        for (int b = 0; b < 8; b++)
            #pragma unroll
            for (int c = 0; c < 4; c++) acc[a][b][c] = 0.f;

    for (int k0 = 0; k0 < K3; k0 += ZBK) {
        #pragma unroll
        for (int r = 0; r < 2; r++) {
            int i = tid + r * 256;
            int m = i >> 2;
            int kk = (i & 3) * 8;
            *(float4*)&As[m][kk] = *(const float4*)&g_za[(ri + m) * K3 + k0 + kk];
            *(float4*)&Bs[m][kk] = *(const float4*)&g_zb[(rj + m) * K3 + k0 + kk];
        }
        __syncthreads();
        #pragma unroll
        for (int kk = 0; kk < ZBK; kk += 16) {
            unsigned a0[2], a1[2], a2[2], a3[2];
            #pragma unroll
            for (int mi = 0; mi < 2; mi++) {
                int row = 32 * wm + 16 * mi;
                a0[mi] = *(const unsigned*)&As[row + g    ][kk + 2 * tg];
                a1[mi] = *(const unsigned*)&As[row + g + 8][kk + 2 * tg];
                a2[mi] = *(const unsigned*)&As[row + g    ][kk + 2 * tg + 8];
                a3[mi] = *(const unsigned*)&As[row + g + 8][kk + 2 * tg + 8];
            }
            #pragma unroll
            for (int nj = 0; nj < 8; nj++) {
                int col = 64 * wn + 8 * nj + g;
                unsigned b0 = *(const unsigned*)&Bs[col][kk + 2 * tg];
                unsigned b1 = *(const unsigned*)&Bs[col][kk + 2 * tg + 8];
                #pragma unroll
                for (int mi = 0; mi < 2; mi++) {
                    asm volatile(
                        "mma.sync.aligned.m16n8k16.row.col.f32.bf16.bf16.f32 "
                        "{%0,%1,%2,%3}, {%4,%5,%6,%7}, {%8,%9}, {%0,%1,%2,%3};"
                        : "+f"(acc[mi][nj][0]), "+f"(acc[mi][nj][1]),
                          "+f"(acc[mi][nj][2]), "+f"(acc[mi][nj][3])
                        : "r"(a0[mi]), "r"(a1[mi]), "r"(a2[mi]), "r"(a3[mi]),
                          "r"(b0), "r"(b1));
                }
            }
        }
        __syncthreads();
    }

    #pragma unroll
    for (int mi = 0; mi < 2; mi++)
        #pragma unroll
        for (int nj = 0; nj < 8; nj++)
            #pragma unroll
            for (int c = 0; c < 4; c++) {
                float v = acc[mi][nj][c];
                float r = 1.0f / (1.0f + __expf(-v));
                acc[mi][nj][c] = (r == r) ? r : 0.0f;
            }

    #pragma unroll
    for (int mi = 0; mi < 2; mi++) {
        int row = ri + 32 * wm + 16 * mi + g;
        #pragma unroll
        for (int nj = 0; nj < 8; nj++) {
            int col = rj + 64 * wn + 8 * nj + 2 * tg;
            *(float2*)&C[(long long)row * NN + col] =
                make_float2(acc[mi][nj][0], acc[mi][nj][1]);
            *(float2*)&C[(long long)(row + 8) * NN + col] =
                make_float2(acc[mi][nj][2], acc[mi][nj][3]);
        }
    }
    if (bi != bj) {
        #pragma unroll
        for (int mi = 0; mi < 2; mi++) {
            int colm = ri + 32 * wm + 16 * mi + g;
            #pragma unroll
            for (int nj = 0; nj < 8; nj++) {
                int rowm = rj + 64 * wn + 8 * nj + 2 * tg;
                C[(long long)rowm * NN + colm]           = acc[mi][nj][0];
                C[(long long)(rowm + 1) * NN + colm]     = acc[mi][nj][1];
                C[(long long)rowm * NN + colm + 8]       = acc[mi][nj][2];
                C[(long long)(rowm + 1) * NN + colm + 8] = acc[mi][nj][3];
            }
        }
    }
}

// ---------------- launch ----------------
extern "C" void kernel_launch(void* const* d_in, const int* in_sizes, int n_in,
                              void* d_out, int out_size) {
    const float* features = (const float*)d_in[0];
    const void*  ei       = d_in[1];
    const float* noise    = (const float*)d_in[2];
    const float* W0       = (const float*)d_in[3];
    const float* b0       = (const float*)d_in[4];
    const float* Wm       = (const float*)d_in[5];
    const float* bm       = (const float*)d_in[6];
    const float* Ws       = (const float*)d_in[7];
    const float* bs       = (const float*)d_in[8];
    int E = in_sizes[1] / 2;
    float* out = (float*)d_out;

    int eb = (E + 255) / 256;

    vg_sniff_zero<<<NN / 256, 256>>>((const unsigned*)ei);       // 1
    vg_build<<<eb, 256>>>(ei, E);                                // 2 (single edge pass)
    vg_dinv<<<NN / 256, 256>>>(bm, bs);                          // 3

    vg_gemm1<<<dim3(NN / 64, 1), 256>>>(features, W0, out);      // 4
    vg_agg1<<<NN / 8, 256>>>(b0, out);                           // 5

    vg_gemm2<<<dim3(NN / 64, 2), 256>>>(Wm, Ws, out);            // 6 (profiled by ncu)
    vg_agg2_z<<<NN / 8, 256>>>(noise, out);                      // 7

    vg_zzt_mma<<<dim3(64, 64), 256>>>(out);                      // 8
}